// round 12
// baseline (speedup 1.0000x reference)
#include <cuda_runtime.h>
#include <cuda_bf16.h>

#define BATCH 256
#define CH 64
#define PLANE 784
#define NPLANES (BATCH*CH)
#define YH_PER_BS 25088
#define YH_TOTAL (BATCH*6*YH_PER_BS)

__device__ __align__(16) float g_lo[(size_t)NPLANES * PLANE];
__device__ __align__(16) float g_hi[(size_t)NPLANES * PLANE];
__device__ __align__(16) float g_ll[(size_t)NPLANES * PLANE];
__device__ __align__(16) float g_yh[(size_t)YH_TOTAL];

#define H0_INIT {-0.0017578f,0.0f,0.0222656f,-0.046875f,-0.0482422f,0.296875f,0.5554688f,0.296875f,-0.0482422f,-0.046875f,0.0222656f,0.0f,-0.0017578f}
#define H1_INIT {-7.06e-05f,0.0f,0.0013419f,-0.0018834f,-0.0071568f,0.023856f,0.0556431f,-0.0516881f,-0.2997576f,0.5594308f,-0.2997576f,-0.0516881f,0.0556431f,0.023856f,-0.0071568f,-0.0018834f,0.0013419f,0.0f,-7.06e-05f}
#define G0_INIT {7.06e-05f,0.0f,-0.0013419f,-0.0018834f,0.0071568f,0.023856f,-0.0556431f,-0.0516881f,0.2997576f,0.5594308f,0.2997576f,-0.0516881f,-0.0556431f,0.023856f,0.0071568f,-0.0018834f,-0.0013419f,0.0f,7.06e-05f}
#define G1_INIT {0.0017578f,0.0f,-0.0222656f,-0.046875f,0.0482422f,0.296875f,-0.5554688f,0.296875f,0.0482422f,-0.046875f,-0.0222656f,0.0f,0.0017578f}

__device__ __forceinline__ int refl28(int p) {
    return p < 0 ? (-1 - p) : (p > 27 ? (55 - p) : p);
}

template <int L, bool ACC>
__device__ __forceinline__ void filt28(const float (&x)[28], float (&y)[28], const float (&h)[L]) {
    constexpr int m = L / 2;
#pragma unroll
    for (int i = 0; i < 28; i++) {
        float a = ACC ? y[i] : 0.0f;
#pragma unroll
        for (int t = 0; t < L; t++)
            if (h[t] != 0.0f) a = fmaf(x[refl28(i + t - m)], h[t], a);
        y[i] = a;
    }
}

// ---- A: depthwise 3x3, channels 0..63, channel-last in/out ----
__global__ void k_dwconv(const float* __restrict__ x, const float* __restrict__ cw,
                         const float* __restrict__ cb, float* __restrict__ out) {
    __shared__ float sx[3][28][64];
    int b = blockIdx.x / 28, h = blockIdx.x % 28;
    const float* xb = x + (size_t)b * PLANE * 128;
    for (int idx = threadIdx.x; idx < 3 * 28 * 64; idx += 256) {
        int cc = idx & 63, ww = (idx >> 6) % 28, rr = idx / (64 * 28);
        int hh = h + rr - 1;
        sx[rr][ww][cc] = (hh >= 0 && hh < 28) ? xb[(size_t)(hh * 28 + ww) * 128 + cc] : 0.0f;
    }
    __syncthreads();
    int c = threadIdx.x & 63, wq = threadIdx.x >> 6;
    float k[9];
#pragma unroll
    for (int t = 0; t < 9; t++) k[t] = cw[c * 9 + t];
    float bias = cb[c];
    for (int w = wq; w < 28; w += 4) {
        float acc = bias;
#pragma unroll
        for (int dy = 0; dy < 3; dy++)
#pragma unroll
            for (int dx = 0; dx < 3; dx++) {
                int ww = w + dx - 1;
                if (ww >= 0 && ww < 28) acc = fmaf(sx[dy][ww][c], k[dy * 3 + dx], acc);
            }
        out[(size_t)(b * PLANE + h * 28 + w) * 128 + c] = acc;
    }
}

// ---- B: forward row filters (W axis), x ch 64..127 -> planar g_lo/g_hi ----
__global__ void k_fwd_rows(const float* __restrict__ x) {
    const float H0[13] = H0_INIT;
    const float H1[19] = H1_INIT;
    __shared__ float slo[64][29], shi[64][29];
    int b = blockIdx.x / 28, h = blockIdx.x % 28;
    int c = threadIdx.x;
    const float* xp = x + (size_t)(b * PLANE + h * 28) * 128 + 64 + c;
    float v[28], lo[28], hi[28];
#pragma unroll
    for (int w = 0; w < 28; w++) v[w] = xp[(size_t)w * 128];
    filt28<13, false>(v, lo, H0);
    filt28<19, false>(v, hi, H1);
#pragma unroll
    for (int w = 0; w < 28; w++) { slo[c][w] = lo[w]; shi[c][w] = hi[w]; }
    __syncthreads();
    int lane = threadIdx.x & 31, warp = threadIdx.x >> 5;
    size_t base = (size_t)b * CH * PLANE + (size_t)h * 28;
    if (lane < 28)
        for (int cc = warp; cc < 64; cc += 2) {
            g_lo[base + (size_t)cc * PLANE + lane] = slo[cc][lane];
            g_hi[base + (size_t)cc * PLANE + lane] = shi[cc][lane];
        }
}

// ---- C: forward column filters + q2c + ll*w_ll. yh layout (b,s,c,i,j,reim) ----
__global__ void k_fwd_cols(const float* __restrict__ w_ll) {
    const float H0[13] = H0_INIT;
    const float H1[19] = H1_INIT;
    __shared__ float slh[28][29], shl[28][29], shh[28][29];
    int bc = blockIdx.x, b = bc >> 6, c = bc & 63;
    int w = threadIdx.x;
    size_t base = (size_t)bc * PLANE;
    if (w < 28) {
        float col[28], oA[28], oB[28];
#pragma unroll
        for (int hh = 0; hh < 28; hh++) col[hh] = g_lo[base + hh * 28 + w];
        filt28<13, false>(col, oA, H0);
        filt28<19, false>(col, oB, H1);
#pragma unroll
        for (int hh = 0; hh < 28; hh++) {
            g_ll[base + hh * 28 + w] = oA[hh] * w_ll[c * PLANE + hh * 28 + w];
            slh[hh][w] = oB[hh];
        }
#pragma unroll
        for (int hh = 0; hh < 28; hh++) col[hh] = g_hi[base + hh * 28 + w];
        filt28<13, false>(col, oA, H0);
        filt28<19, false>(col, oB, H1);
#pragma unroll
        for (int hh = 0; hh < 28; hh++) { shl[hh][w] = oA[hh]; shh[hh][w] = oB[hh]; }
    }
    __syncthreads();
    const float is = 0.70710678118654752440f;
    float2* yh2 = reinterpret_cast<float2*>(g_yh);
    size_t pb = ((size_t)b * 384 + c) * 196;
    for (int p = w; p < 196; p += 32) {
        int i = p / 14, j = p - i * 14;
        float a, bb, cc, dd;
        a = slh[2*i][2*j]*is; bb = slh[2*i][2*j+1]*is; cc = slh[2*i+1][2*j]*is; dd = slh[2*i+1][2*j+1]*is;
        float2 lhp = make_float2(a-dd, bb+cc), lhq = make_float2(a+dd, bb-cc);
        a = shh[2*i][2*j]*is; bb = shh[2*i][2*j+1]*is; cc = shh[2*i+1][2*j]*is; dd = shh[2*i+1][2*j+1]*is;
        float2 hhp = make_float2(a-dd, bb+cc), hhq = make_float2(a+dd, bb-cc);
        a = shl[2*i][2*j]*is; bb = shl[2*i][2*j+1]*is; cc = shl[2*i+1][2*j]*is; dd = shl[2*i+1][2*j+1]*is;
        float2 hlp = make_float2(a-dd, bb+cc), hlq = make_float2(a+dd, bb-cc);
        yh2[pb + 0*12544 + p] = lhp;
        yh2[pb + 1*12544 + p] = hhp;
        yh2[pb + 2*12544 + p] = hlp;
        yh2[pb + 3*12544 + p] = hlq;
        yh2[pb + 4*12544 + p] = hhq;
        yh2[pb + 5*12544 + p] = lhq;
    }
}

// ---- D: fused channel mix + token mix per (b,subband) ----
#define TP 393
#define SMEM_MIX (41264 * 4)

__global__ __launch_bounds__(512, 1) void k_mix(
    const float* __restrict__ w_lh1, const float* __restrict__ w_lh2,
    const float* __restrict__ b_lh1, const float* __restrict__ b_lh2,
    const float* __restrict__ w_t1, const float* __restrict__ w_t2,
    const float* __restrict__ b_t1, const float* __restrict__ b_t2) {
    extern __shared__ float sm[];
    float* T = sm;
    float* wl1 = T + 64 * TP;
    float* wl2 = wl1 + 2048;
    float* bl1 = wl2 + 2048;
    float* bl2 = bl1 + 128;
    float* wt1 = bl2 + 128;
    float* wt2 = wt1 + 5488;
    float* bt1 = wt2 + 5488;
    float* bt2 = bt1 + 392;
    int tid = threadIdx.x;
    for (int t = tid; t < 2048; t += 512) { wl1[t] = w_lh1[t]; wl2[t] = w_lh2[t]; }
    for (int t = tid; t < 5488; t += 512) { wt1[t] = w_t1[t]; wt2[t] = w_t2[t]; }
    if (tid < 128) { bl1[tid] = b_lh1[tid]; bl2[tid] = b_lh2[tid]; }
    for (int t = tid; t < 392; t += 512) { bt1[t] = b_t1[t]; bt2[t] = b_t2[t]; }
    const float* src = g_yh + (size_t)blockIdx.x * YH_PER_BS;
    for (int idx = tid; idx < YH_PER_BS; idx += 512) {
        int c = idx / 392, r = idx - c * 392;
        T[c * TP + r] = src[idx];
    }
    __syncthreads();
    // channel mixing: block-diagonal 16x16 complex, 2 layers, in-place
    for (int item = tid; item < 784; item += 512) {
        int nb = item / 196, p = item - nb * 196, p2 = p * 2;
        float xr[16], xi[16], s1r[16], s1i[16];
#pragma unroll
        for (int d = 0; d < 16; d++) {
            int off = (nb * 16 + d) * TP + p2;
            xr[d] = T[off]; xi[d] = T[off + 1];
        }
#pragma unroll
        for (int k = 0; k < 16; k++) {
            float ar = bl1[nb*16+k], ai = bl1[64+nb*16+k];
#pragma unroll
            for (int d = 0; d < 16; d++) {
                float w0 = wl1[nb*256 + d*16 + k], w1 = wl1[1024 + nb*256 + d*16 + k];
                ar = fmaf(xr[d], w0, fmaf(-xi[d], w1, ar));
                ai = fmaf(xr[d], w1, fmaf(xi[d], w0, ai));
            }
            s1r[k] = fmaxf(ar, 0.0f); s1i[k] = fmaxf(ai, 0.0f);
        }
#pragma unroll
        for (int k = 0; k < 16; k++) {
            float ar = bl2[nb*16+k], ai = bl2[64+nb*16+k];
#pragma unroll
            for (int d = 0; d < 16; d++) {
                float w0 = wl2[nb*256 + d*16 + k], w1 = wl2[1024 + nb*256 + d*16 + k];
                ar = fmaf(s1r[d], w0, fmaf(-s1i[d], w1, ar));
                ai = fmaf(s1r[d], w1, fmaf(s1i[d], w0, ai));
            }
            int off = (nb * 16 + k) * TP + p2;
            T[off] = ar; T[off + 1] = ai;
        }
    }
    __syncthreads();
    // token mixing: per (c,i) row, 14x14 complex, 2 layers, in-place
    for (int row = tid; row < 896; row += 512) {
        int i = row >> 6, c = row & 63, cb = c * TP + i * 28;
        float zr[14], zi[14], s1r[14], s1i[14];
#pragma unroll
        for (int j = 0; j < 14; j++) { zr[j] = T[cb + 2*j]; zi[j] = T[cb + 2*j + 1]; }
#pragma unroll
        for (int k = 0; k < 14; k++) {
            float ar = bt1[i*14+k], ai = bt1[196 + i*14+k];
#pragma unroll
            for (int j = 0; j < 14; j++) {
                float w0 = wt1[(i*14+j)*14+k], w1 = wt1[2744 + (i*14+j)*14+k];
                ar = fmaf(zr[j], w0, fmaf(-zi[j], w1, ar));
                ai = fmaf(zr[j], w1, fmaf(zi[j], w0, ai));
            }
            s1r[k] = fmaxf(ar, 0.0f); s1i[k] = fmaxf(ai, 0.0f);
        }
#pragma unroll
        for (int k = 0; k < 14; k++) {
            float ar = bt2[i*14+k], ai = bt2[196 + i*14+k];
#pragma unroll
            for (int j = 0; j < 14; j++) {
                float w0 = wt2[(i*14+j)*14+k], w1 = wt2[2744 + (i*14+j)*14+k];
                ar = fmaf(s1r[j], w0, fmaf(-s1i[j], w1, ar));
                ai = fmaf(s1r[j], w1, fmaf(s1i[j], w0, ai));
            }
            T[cb + 2*k] = ar; T[cb + 2*k + 1] = ai;
        }
    }
    __syncthreads();
    float* dst = g_yh + (size_t)blockIdx.x * YH_PER_BS;
    for (int idx = tid; idx < YH_PER_BS; idx += 512) {
        int c = idx / 392, r = idx - c * 392;
        dst[idx] = T[c * TP + r];
    }
}

// ---- E: inverse column filters with inline c2q; writes g_lo/g_hi = lo2/hi2 ----
__global__ void k_inv_cols() {
    const float G0[19] = G0_INIT;
    const float G1[13] = G1_INIT;
    int bc = blockIdx.x, b = bc >> 6, c = bc & 63;
    int w = threadIdx.x;
    if (w >= 28) return;
    size_t base = (size_t)bc * PLANE;
    int j = w >> 1, dx = w & 1;
    const float2* yh2 = reinterpret_cast<const float2*>(g_yh);
    size_t pb = ((size_t)b * 384 + c) * 196;
    const float is = 0.70710678118654752440f;
    float cA[28], cB[28], outv[28];
#pragma unroll
    for (int hh = 0; hh < 28; hh++) cA[hh] = g_ll[base + hh * 28 + w];
#pragma unroll
    for (int i = 0; i < 14; i++) {
        float2 v1 = yh2[pb + 0*12544 + i*14 + j];
        float2 v2 = yh2[pb + 5*12544 + i*14 + j];
        if (dx == 0) { cB[2*i] = (v1.x + v2.x)*is; cB[2*i+1] = (v1.y - v2.y)*is; }
        else         { cB[2*i] = (v1.y + v2.y)*is; cB[2*i+1] = (v2.x - v1.x)*is; }
    }
    filt28<19, false>(cA, outv, G0);
    filt28<13, true>(cB, outv, G1);
#pragma unroll
    for (int hh = 0; hh < 28; hh++) g_lo[base + hh * 28 + w] = outv[hh];
#pragma unroll
    for (int i = 0; i < 14; i++) {
        float2 v1 = yh2[pb + 2*12544 + i*14 + j];
        float2 v2 = yh2[pb + 3*12544 + i*14 + j];
        if (dx == 0) { cA[2*i] = (v1.x + v2.x)*is; cA[2*i+1] = (v1.y - v2.y)*is; }
        else         { cA[2*i] = (v1.y + v2.y)*is; cA[2*i+1] = (v2.x - v1.x)*is; }
        float2 u1 = yh2[pb + 1*12544 + i*14 + j];
        float2 u2 = yh2[pb + 4*12544 + i*14 + j];
        if (dx == 0) { cB[2*i] = (u1.x + u2.x)*is; cB[2*i+1] = (u1.y - u2.y)*is; }
        else         { cB[2*i] = (u1.y + u2.y)*is; cB[2*i+1] = (u2.x - u1.x)*is; }
    }
    filt28<19, false>(cA, outv, G0);
    filt28<13, true>(cB, outv, G1);
#pragma unroll
    for (int hh = 0; hh < 28; hh++) g_hi[base + hh * 28 + w] = outv[hh];
}

// ---- F: inverse row filters -> out channels 64..127 ----
__global__ void k_inv_rows(float* __restrict__ out) {
    const float G0[19] = G0_INIT;
    const float G1[13] = G1_INIT;
    __shared__ float slo[64][29], shi[64][29];
    int b = blockIdx.x / 28, h = blockIdx.x % 28;
    int lane = threadIdx.x & 31, warp = threadIdx.x >> 5;
    size_t base = (size_t)b * CH * PLANE + (size_t)h * 28;
    if (lane < 28)
        for (int cc = warp; cc < 64; cc += 2) {
            slo[cc][lane] = g_lo[base + (size_t)cc * PLANE + lane];
            shi[cc][lane] = g_hi[base + (size_t)cc * PLANE + lane];
        }
    __syncthreads();
    int c = threadIdx.x;
    float vlo[28], vhi[28], res[28];
#pragma unroll
    for (int w = 0; w < 28; w++) { vlo[w] = slo[c][w]; vhi[w] = shi[c][w]; }
    filt28<19, false>(vlo, res, G0);
    filt28<13, true>(vhi, res, G1);
    float* op = out + (size_t)(b * PLANE + h * 28) * 128 + 64 + c;
#pragma unroll
    for (int w = 0; w < 28; w++) op[(size_t)w * 128] = res[w];
}

extern "C" void kernel_launch(void* const* d_in, const int* in_sizes, int n_in,
                              void* d_out, int out_size) {
    (void)in_sizes; (void)n_in; (void)out_size;
    const float* x      = (const float*)d_in[0];
    const float* conv_w = (const float*)d_in[1];
    const float* conv_b = (const float*)d_in[2];
    const float* w_ll   = (const float*)d_in[3];
    const float* w_lh1  = (const float*)d_in[4];
    const float* w_lh2  = (const float*)d_in[5];
    const float* b_lh1  = (const float*)d_in[6];
    const float* b_lh2  = (const float*)d_in[7];
    const float* w_t1   = (const float*)d_in[8];
    const float* w_t2   = (const float*)d_in[9];
    const float* b_t1   = (const float*)d_in[10];
    const float* b_t2   = (const float*)d_in[11];
    float* out = (float*)d_out;
    cudaFuncSetAttribute(k_mix, cudaFuncAttributeMaxDynamicSharedMemorySize, SMEM_MIX);
    k_dwconv<<<BATCH * 28, 256>>>(x, conv_w, conv_b, out);
    k_fwd_rows<<<BATCH * 28, 64>>>(x);
    k_fwd_cols<<<BATCH * 64, 32>>>(w_ll);
    k_mix<<<BATCH * 6, 512, SMEM_MIX>>>(w_lh1, w_lh2, b_lh1, b_lh2, w_t1, w_t2, b_t1, b_t2);
    k_inv_cols<<<BATCH * 64, 32>>>();
    k_inv_rows<<<BATCH * 28, 64>>>(out);
}